// round 15
// baseline (speedup 1.0000x reference)
#include <cuda_runtime.h>
#include <cuda_fp16.h>
#include <cstdint>

// Problem constants (Head_84533546320520)
#define BATCH 8
#define SEQ   2048
#define DEMB  1024
#define HEAD  64
#define NROWS (BATCH * SEQ)   // 16384
#define SCALE 0.125f          // HEAD^-0.5
#define LOG2E 1.4426950408889634f

// fp16 scratch: projected q (pre-scaled by SCALE*log2e), k, v
__device__ __half g_qh[NROWS * HEAD];
__device__ __half g_kh[NROWS * HEAD];
__device__ __half g_vh[NROWS * HEAD];

// Pre-converted weights (single fp16)
__device__ __half g_wh[3][DEMB * HEAD];

// ===========================================================================
// helpers
// ===========================================================================
__device__ __forceinline__ uint32_t smem_to_u32(const void* p) {
    uint32_t a;
    asm("{ .reg .u64 t; cvta.to.shared.u64 t, %1; cvt.u32.u64 %0, t; }"
        : "=r"(a) : "l"(p));
    return a;
}
__device__ __forceinline__ void ldsm_x4(uint32_t* r, uint32_t addr) {
    asm volatile("ldmatrix.sync.aligned.m8n8.x4.shared.b16 {%0,%1,%2,%3}, [%4];"
        : "=r"(r[0]), "=r"(r[1]), "=r"(r[2]), "=r"(r[3]) : "r"(addr));
}
__device__ __forceinline__ void ldsm_x4_trans(uint32_t* r, uint32_t addr) {
    asm volatile("ldmatrix.sync.aligned.m8n8.x4.trans.shared.b16 {%0,%1,%2,%3}, [%4];"
        : "=r"(r[0]), "=r"(r[1]), "=r"(r[2]), "=r"(r[3]) : "r"(addr));
}
__device__ __forceinline__ void mma_f16(float* d, const uint32_t* a, const uint32_t* b) {
    asm volatile(
        "mma.sync.aligned.m16n8k16.row.col.f32.f16.f16.f32 "
        "{%0,%1,%2,%3}, {%4,%5,%6,%7}, {%8,%9}, {%0,%1,%2,%3};"
        : "+f"(d[0]), "+f"(d[1]), "+f"(d[2]), "+f"(d[3])
        : "r"(a[0]), "r"(a[1]), "r"(a[2]), "r"(a[3]), "r"(b[0]), "r"(b[1]));
}
__device__ __forceinline__ uint32_t cvt2h(float x, float y) {
    __half2 hb = __float22half2_rn(make_float2(x, y));
    return *reinterpret_cast<uint32_t*>(&hb);
}
__device__ __forceinline__ void cp_async16(uint32_t saddr, const void* gaddr) {
    asm volatile("cp.async.cg.shared.global [%0], [%1], 16;"
        :: "r"(saddr), "l"(gaddr) : "memory");
}
#define CP_COMMIT()  asm volatile("cp.async.commit_group;" ::: "memory")
#define CP_WAIT(n)   asm volatile("cp.async.wait_group %0;" :: "n"(n) : "memory")

// ===========================================================================
// Kernel 0: convert W to fp16. grid (64, 3), block 256.
// ===========================================================================
__global__ __launch_bounds__(256) void wsplit_kernel(
    const float* __restrict__ Wq, const float* __restrict__ Wk,
    const float* __restrict__ Wv)
{
    const int which = blockIdx.y;
    const float* __restrict__ W = (which == 0) ? Wq : (which == 1) ? Wk : Wv;
    int idx = blockIdx.x * 256 + threadIdx.x;
    float4 t = reinterpret_cast<const float4*>(W)[idx];
    *reinterpret_cast<uint2*>(&g_wh[which][idx * 4]) =
        make_uint2(cvt2h(t.x, t.y), cvt2h(t.z, t.w));
}

// ===========================================================================
// Kernel 1: projections, A-stores moved into the MMA shadow:
// round c: sync'd A(c)/B(c) -> store A(c+1) + MMA(c) + LDG/cvt(c+2) + cpB(c+2).
// A double-buffered, B quad-buffered. grid = (NROWS/128, 3), block = 256.
// ===========================================================================
#define KC 64
#define NCH (DEMB / KC)           // 16
#define APAD 72
#define ABUF (128 * APAD * 2)     // 18432 B
#define BBUF (64 * APAD * 2)      // 9216 B
#define PROJ_SMEM (2 * ABUF + 4 * BBUF)   // 73728 B

__global__ __launch_bounds__(256) void proj_mma_kernel(
    const float* __restrict__ q, const float* __restrict__ k,
    const float* __restrict__ v)
{
    extern __shared__ __align__(16) char smc[];
    const uint32_t base = smem_to_u32(smc);
    const uint32_t bBase = base + 2 * ABUF;

    const int which = blockIdx.y;
    const float* __restrict__ X = (which == 0) ? q : (which == 1) ? k : v;
    const __half* __restrict__ Wh = g_wh[which];
    const float postmul = (which == 0) ? (SCALE * LOG2E) : 1.0f;

    const int tid = threadIdx.x;
    const int wid = tid >> 5;
    const int lane = tid & 31;
    const int l16 = lane & 15;
    const int hi8 = (lane >> 4) << 3;
    const int row0 = blockIdx.x * 128;
    const int m0 = wid * 16;

    float4 rawX[8];     // fp32 X data for chunk c+2
    uint2  hX[8];       // converted fp16 for chunk c+1

    auto loadA = [&](int k0) {
        #pragma unroll
        for (int i = 0; i < 8; i++) {
            int idx = tid + i * 256;
            int r = idx >> 4, cg = idx & 15;
            rawX[i] = *reinterpret_cast<const float4*>(
                X + (size_t)(row0 + r) * DEMB + k0 + cg * 4);
        }
    };
    auto cvtA = [&]() {
        #pragma unroll
        for (int i = 0; i < 8; i++) {
            hX[i].x = cvt2h(rawX[i].x, rawX[i].y);
            hX[i].y = cvt2h(rawX[i].z, rawX[i].w);
        }
    };
    auto storeA = [&](int s) {
        const uint32_t aB = base + s * ABUF;
        #pragma unroll
        for (int i = 0; i < 8; i++) {
            int idx = tid + i * 256;
            int r = idx >> 4, cg = idx & 15;
            uint32_t off = (uint32_t)(r * APAD + cg * 4) * 2;
            asm volatile("st.shared.v2.b32 [%0], {%1, %2};"
                :: "r"(aB + off), "r"(hX[i].x), "r"(hX[i].y) : "memory");
        }
    };
    auto cpB = [&](int c) {
        const uint32_t bB = bBase + (c & 3) * BBUF;
        const int k0 = c * KC;
        #pragma unroll
        for (int i = 0; i < 2; i++) {
            int rem = tid + i * 256;
            int r = rem >> 3, cq = rem & 7;
            cp_async16(bB + r * 144 + cq * 16,
                       Wh + (size_t)(k0 + r) * HEAD + cq * 8);
        }
        CP_COMMIT();
    };

    float acc[8][4] = {};

    // prologue: chunk 0 staged in abuf0; hX = chunk 1; B0,B1 in flight
    loadA(0); cvtA(); storeA(0);
    loadA(KC); cvtA();
    cpB(0); cpB(1);
    CP_WAIT(0);
    __syncthreads();

    for (int c = 0; c < NCH; c++) {
        const int s = c & 1;
        // entry invariant: A(c) in abuf s, B(c) in bbuf c&3, all visible;
        // hX holds chunk c+1 (fp16)
        if (c + 1 < NCH) storeA(s ^ 1);      // overlaps MMA(c) below

        const uint32_t aB = base + s * ABUF;
        const uint32_t bB = bBase + (c & 3) * BBUF;
        #pragma unroll
        for (int kk = 0; kk < 4; kk++) {
            uint32_t af[4];
            uint32_t aoff = (uint32_t)(((m0 + l16) * APAD + kk * 16 + hi8) * 2);
            ldsm_x4(af, aB + aoff);
            #pragma unroll
            for (int nb = 0; nb < 4; nb++) {
                uint32_t bh[4];
                uint32_t boff = (uint32_t)(((kk * 16 + l16) * APAD + nb * 16 + hi8) * 2);
                ldsm_x4_trans(bh, bB + boff);
                mma_f16(acc[2 * nb + 0], af, bh + 0);
                mma_f16(acc[2 * nb + 1], af, bh + 2);
            }
        }

        if (c + 2 < NCH) {
            loadA((c + 2) * KC);     // LDGs issue under MMA execution
            cpB(c + 2);              // bbuf (c+2)&3 — disjoint from bbuf c&3
            cvtA();                  // convert chunk c+2 -> hX (after LDG)
        }
        if (c + 1 < NCH) {
            if (c + 2 < NCH) { CP_WAIT(1); }   // B(c+1) done; B(c+2) may fly
            else            { CP_WAIT(0); }
            __syncthreads();         // A(c+1) stores visible; MMA(c) reads drained
        }
    }

    const int r = lane >> 2;
    const int cc = (lane & 3) * 2;
    const size_t rA = (size_t)(row0 + m0 + r) * HEAD;
    const size_t rB = (size_t)(row0 + m0 + r + 8) * HEAD;
    __half* outH = (which == 0) ? g_qh : (which == 1) ? g_kh : g_vh;
    #pragma unroll
    for (int j = 0; j < 8; j++) {
        *reinterpret_cast<uint32_t*>(&outH[rA + j * 8 + cc]) =
            cvt2h(acc[j][0] * postmul, acc[j][1] * postmul);
        *reinterpret_cast<uint32_t*>(&outH[rB + j * 8 + cc]) =
            cvt2h(acc[j][2] * postmul, acc[j][3] * postmul);
    }
}

// ===========================================================================
// Kernel 2: flash attention (UNCHANGED from R14 win): 128-wide key tiles,
// 3-stage ring, PV one round behind, exp2 softmax.
// grid = (SEQ/64, BATCH), block = 128.
// ===========================================================================
#define AP 72
#define BUF2 (128 * AP * 2)
#define STAGE2 (2 * BUF2)
#define NST 3
#define ATTN_SMEM (NST * STAGE2 + 512)  // 111104 B
#define NT2 (SEQ / 128)

__global__ __launch_bounds__(128) void attn_mma_kernel(
    const int* __restrict__ mask, float* __restrict__ out)
{
    extern __shared__ __align__(16) char smc[];
    const uint32_t smemB = smem_to_u32(smc);
    float* biasS = reinterpret_cast<float*>(smc + NST * STAGE2);

    const int b  = blockIdx.y;
    const int q0 = blockIdx.x * 64;
    const size_t base = (size_t)b * SEQ * HEAD;

    const int tid  = threadIdx.x;
    const int wid  = tid >> 5;
    const int lane = tid & 31;
    const int l16  = lane & 15;
    const int hi8  = (lane >> 4) << 3;
    const int m0   = wid * 16;
    const int c2   = (lane & 3) * 2;

    const int krow = (lane & 7) + ((lane & 16) >> 1);
    const int hcol = (lane & 8);

    #pragma unroll
    for (int i = 0; i < 4; i++) {
        int idx = tid + i * 128;
        int r = idx >> 3, cq = idx & 7;
        uint4 th = *reinterpret_cast<const uint4*>(g_qh + base + (size_t)(q0 + r) * HEAD + cq * 8);
        *reinterpret_cast<uint4*>(smc + r * 144 + cq * 16) = th;
    }
    __syncthreads();
    uint32_t qh[4][4];
    #pragma unroll
    for (int kh = 0; kh < 4; kh++) {
        uint32_t aoff = (uint32_t)(((m0 + l16) * AP + kh * 16 + hi8) * 2);
        ldsm_x4(qh[kh], smemB + aoff);
    }
    __syncthreads();

    const __half* srcs[2] = {g_kh + base, g_vh + base};
    auto prefetch = [&](int t) {
        const uint32_t st = smemB + (t % NST) * STAGE2;
        const int k0 = t * 128;
        #pragma unroll
        for (int i = 0; i < 16; i++) {
            const int buf = i >> 3;
            int rem = tid + (i & 7) * 128;
            int r = rem >> 3, cq = rem & 7;
            cp_async16(st + buf * BUF2 + r * 144 + cq * 16,
                       srcs[buf] + (size_t)(k0 + r) * HEAD + cq * 8);
        }
        CP_COMMIT();
    };

    prefetch(0);

    const float NEG_INF = __int_as_float(0xff800000);
    float mR0 = NEG_INF, mR1 = NEG_INF, lS0 = 0.f, lS1 = 0.f;
    float o[8][4] = {};
    uint32_t pPrev[8][4];

    for (int kt = 0; kt < NT2; kt++) {
        const uint32_t stK = smemB + (kt % NST) * STAGE2;

        CP_WAIT(0);
        biasS[tid] = (mask[(size_t)b * SEQ + kt * 128 + tid] != 0) ? 0.f : -1e30f;
        __syncthreads();
        if (kt + 1 < NT2) prefetch(kt + 1);

        float sF[16][4] = {};
        #pragma unroll
        for (int kh = 0; kh < 4; kh++) {
            #pragma unroll
            for (int nb = 0; nb < 8; nb++) {
                uint32_t bh[4];
                uint32_t boff = (uint32_t)(((nb * 16 + krow) * AP + kh * 16 + hcol) * 2);
                ldsm_x4(bh, stK + boff);
                mma_f16(sF[2 * nb],     qh[kh], bh);
                mma_f16(sF[2 * nb + 1], qh[kh], bh + 2);
            }
        }

        if (kt > 0) {
            const uint32_t stVp = smemB + ((kt - 1) % NST) * STAGE2 + BUF2;
            #pragma unroll
            for (int kb = 0; kb < 8; kb++) {
                #pragma unroll
                for (int nb = 0; nb < 4; nb++) {
                    uint32_t vh[4];
                    uint32_t boff = (uint32_t)(((kb * 16 + l16) * AP + nb * 16 + hi8) * 2);
                    ldsm_x4_trans(vh, stVp + boff);
                    mma_f16(o[2 * nb],     pPrev[kb], vh);
                    mma_f16(o[2 * nb + 1], pPrev[kb], vh + 2);
                }
            }
        }

        float mx0 = NEG_INF, mx1 = NEG_INF;
        #pragma unroll
        for (int j = 0; j < 16; j++) {
            float2 bv = *reinterpret_cast<float2*>(&biasS[j * 8 + c2]);
            sF[j][0] += bv.x; sF[j][1] += bv.y; sF[j][2] += bv.x; sF[j][3] += bv.y;
            mx0 = fmaxf(mx0, fmaxf(sF[j][0], sF[j][1]));
            mx1 = fmaxf(mx1, fmaxf(sF[j][2], sF[j][3]));
        }
        mx0 = fmaxf(mx0, __shfl_xor_sync(0xffffffffu, mx0, 1));
        mx0 = fmaxf(mx0, __shfl_xor_sync(0xffffffffu, mx0, 2));
        mx1 = fmaxf(mx1, __shfl_xor_sync(0xffffffffu, mx1, 1));
        mx1 = fmaxf(mx1, __shfl_xor_sync(0xffffffffu, mx1, 2));
        float mn0 = fmaxf(mR0, mx0), mn1 = fmaxf(mR1, mx1);
        float a0 = exp2f(mR0 - mn0), a1 = exp2f(mR1 - mn1);
        float sm0 = 0.f, sm1 = 0.f;
        #pragma unroll
        for (int j = 0; j < 16; j++) {
            sF[j][0] = exp2f(sF[j][0] - mn0);
            sF[j][1] = exp2f(sF[j][1] - mn0);
            sF[j][2] = exp2f(sF[j][2] - mn1);
            sF[j][3] = exp2f(sF[j][3] - mn1);
            sm0 += sF[j][0] + sF[j][1];
            sm1 += sF[j][2] + sF[j][3];
        }
        sm0 += __shfl_xor_sync(0xffffffffu, sm0, 1);
        sm0 += __shfl_xor_sync(0xffffffffu, sm0, 2);
        sm1 += __shfl_xor_sync(0xffffffffu, sm1, 1);
        sm1 += __shfl_xor_sync(0xffffffffu, sm1, 2);
        lS0 = lS0 * a0 + sm0; lS1 = lS1 * a1 + sm1;
        mR0 = mn0; mR1 = mn1;
        #pragma unroll
        for (int j = 0; j < 8; j++) {
            o[j][0] *= a0; o[j][1] *= a0; o[j][2] *= a1; o[j][3] *= a1;
        }

        #pragma unroll
        for (int kb = 0; kb < 8; kb++) {
            pPrev[kb][0] = cvt2h(sF[2 * kb][0],     sF[2 * kb][1]);
            pPrev[kb][1] = cvt2h(sF[2 * kb][2],     sF[2 * kb][3]);
            pPrev[kb][2] = cvt2h(sF[2 * kb + 1][0], sF[2 * kb + 1][1]);
            pPrev[kb][3] = cvt2h(sF[2 * kb + 1][2], sF[2 * kb + 1][3]);
        }
        __syncthreads();
    }

    {
        const uint32_t stVp = smemB + ((NT2 - 1) % NST) * STAGE2 + BUF2;
        #pragma unroll
        for (int kb = 0; kb < 8; kb++) {
            #pragma unroll
            for (int nb = 0; nb < 4; nb++) {
                uint32_t vh[4];
                uint32_t boff = (uint32_t)(((kb * 16 + l16) * AP + nb * 16 + hi8) * 2);
                ldsm_x4_trans(vh, stVp + boff);
                mma_f16(o[2 * nb],     pPrev[kb], vh);
                mma_f16(o[2 * nb + 1], pPrev[kb], vh + 2);
            }
        }
    }

    float inv0 = 1.f / lS0, inv1 = 1.f / lS1;
    int rowA = b * SEQ + q0 + m0 + (lane >> 2);
    #pragma unroll
    for (int j = 0; j < 8; j++) {
        *reinterpret_cast<float2*>(out + (size_t)rowA * HEAD + j * 8 + c2) =
            make_float2(o[j][0] * inv0, o[j][1] * inv0);
        *reinterpret_cast<float2*>(out + (size_t)(rowA + 8) * HEAD + j * 8 + c2) =
            make_float2(o[j][2] * inv1, o[j][3] * inv1);
    }
}

// ---------------------------------------------------------------------------
extern "C" void kernel_launch(void* const* d_in, const int* in_sizes, int n_in,
                              void* d_out, int out_size)
{
    const void* big[3]   = {0, 0, 0};
    const void* small[3] = {0, 0, 0};
    const void* mk = 0;
    int nb = 0, ns = 0;
    for (int i = 0; i < n_in; i++) {
        if (in_sizes[i] == NROWS * DEMB)      { if (nb < 3) big[nb++] = d_in[i]; }
        else if (in_sizes[i] == DEMB * HEAD)  { if (ns < 3) small[ns++] = d_in[i]; }
        else if (in_sizes[i] == BATCH * SEQ)  { mk = d_in[i]; }
    }
    const float* q  = (const float*)big[0];
    const float* k  = (const float*)big[1];
    const float* v  = (const float*)big[2];
    const float* Wq = (const float*)small[0];
    const float* Wk = (const float*)small[1];
    const float* Wv = (const float*)small[2];
    const int*   mask = (const int*)mk;
    float* out = (float*)d_out;

    static bool attr_set = false;
    if (!attr_set) {
        cudaFuncSetAttribute(proj_mma_kernel, cudaFuncAttributeMaxDynamicSharedMemorySize, PROJ_SMEM);
        cudaFuncSetAttribute(attn_mma_kernel, cudaFuncAttributeMaxDynamicSharedMemorySize, ATTN_SMEM);
        attr_set = true;
    }

    wsplit_kernel<<<dim3(64, 3), 256>>>(Wq, Wk, Wv);
    proj_mma_kernel<<<dim3(NROWS / 128, 3), 256, PROJ_SMEM>>>(q, k, v);
    attn_mma_kernel<<<dim3(SEQ / 64, BATCH), 128, ATTN_SMEM>>>(mask, out);
}

// round 16
// speedup vs baseline: 1.0896x; 1.0896x over previous
#include <cuda_runtime.h>
#include <cuda_fp16.h>
#include <cstdint>

// Problem constants (Head_84533546320520)
#define BATCH 8
#define SEQ   2048
#define DEMB  1024
#define HEAD  64
#define NROWS (BATCH * SEQ)   // 16384
#define SCALE 0.125f          // HEAD^-0.5
#define LOG2E 1.4426950408889634f

// fp16 scratch: projected q (pre-scaled by SCALE*log2e), k, v
__device__ __half g_qh[NROWS * HEAD];
__device__ __half g_kh[NROWS * HEAD];
__device__ __half g_vh[NROWS * HEAD];

// Pre-converted weights (single fp16)
__device__ __half g_wh[3][DEMB * HEAD];

// ===========================================================================
// helpers
// ===========================================================================
__device__ __forceinline__ uint32_t smem_to_u32(const void* p) {
    uint32_t a;
    asm("{ .reg .u64 t; cvta.to.shared.u64 t, %1; cvt.u32.u64 %0, t; }"
        : "=r"(a) : "l"(p));
    return a;
}
__device__ __forceinline__ void ldsm_x4(uint32_t* r, uint32_t addr) {
    asm volatile("ldmatrix.sync.aligned.m8n8.x4.shared.b16 {%0,%1,%2,%3}, [%4];"
        : "=r"(r[0]), "=r"(r[1]), "=r"(r[2]), "=r"(r[3]) : "r"(addr));
}
__device__ __forceinline__ void ldsm_x4_trans(uint32_t* r, uint32_t addr) {
    asm volatile("ldmatrix.sync.aligned.m8n8.x4.trans.shared.b16 {%0,%1,%2,%3}, [%4];"
        : "=r"(r[0]), "=r"(r[1]), "=r"(r[2]), "=r"(r[3]) : "r"(addr));
}
__device__ __forceinline__ void mma_f16(float* d, const uint32_t* a, const uint32_t* b) {
    asm volatile(
        "mma.sync.aligned.m16n8k16.row.col.f32.f16.f16.f32 "
        "{%0,%1,%2,%3}, {%4,%5,%6,%7}, {%8,%9}, {%0,%1,%2,%3};"
        : "+f"(d[0]), "+f"(d[1]), "+f"(d[2]), "+f"(d[3])
        : "r"(a[0]), "r"(a[1]), "r"(a[2]), "r"(a[3]), "r"(b[0]), "r"(b[1]));
}
__device__ __forceinline__ uint32_t cvt2h(float x, float y) {
    __half2 hb = __float22half2_rn(make_float2(x, y));
    return *reinterpret_cast<uint32_t*>(&hb);
}
// 1-instruction MUFU exp2 (error ~2^-21, negligible vs 6.7e-4 budget)
__device__ __forceinline__ float ex2(float x) {
    float y;
    asm("ex2.approx.ftz.f32 %0, %1;" : "=f"(y) : "f"(x));
    return y;
}
__device__ __forceinline__ void cp_async16(uint32_t saddr, const void* gaddr) {
    asm volatile("cp.async.cg.shared.global [%0], [%1], 16;"
        :: "r"(saddr), "l"(gaddr) : "memory");
}
#define CP_COMMIT()  asm volatile("cp.async.commit_group;" ::: "memory")
#define CP_WAIT(n)   asm volatile("cp.async.wait_group %0;" :: "n"(n) : "memory")

// ===========================================================================
// Kernel 0: convert W to fp16. grid (64, 3), block 256.
// ===========================================================================
__global__ __launch_bounds__(256) void wsplit_kernel(
    const float* __restrict__ Wq, const float* __restrict__ Wk,
    const float* __restrict__ Wv)
{
    const int which = blockIdx.y;
    const float* __restrict__ W = (which == 0) ? Wq : (which == 1) ? Wk : Wv;
    int idx = blockIdx.x * 256 + threadIdx.x;
    float4 t = reinterpret_cast<const float4*>(W)[idx];
    *reinterpret_cast<uint2*>(&g_wh[which][idx * 4]) =
        make_uint2(cvt2h(t.x, t.y), cvt2h(t.z, t.w));
}

// ===========================================================================
// Kernel 1: projections (R12/R14-exact winner, FROZEN).
// q epilogue pre-scales by SCALE*LOG2E for the exp2 softmax.
// grid = (NROWS/128, 3), block = 256.
// ===========================================================================
#define KC 64
#define NCH (DEMB / KC)
#define APAD 72
#define ABUF (128 * APAD * 2)
#define BBUF (64 * APAD * 2)
#define PROJ_SMEM (2 * ABUF + 2 * BBUF)   // 55296 B

__global__ __launch_bounds__(256) void proj_mma_kernel(
    const float* __restrict__ q, const float* __restrict__ k,
    const float* __restrict__ v)
{
    extern __shared__ __align__(16) char smc[];
    const uint32_t base = smem_to_u32(smc);
    const uint32_t bBase = base + 2 * ABUF;

    const int which = blockIdx.y;
    const float* __restrict__ X = (which == 0) ? q : (which == 1) ? k : v;
    const __half* __restrict__ Wh = g_wh[which];
    const float postmul = (which == 0) ? (SCALE * LOG2E) : 1.0f;

    const int tid = threadIdx.x;
    const int wid = tid >> 5;
    const int lane = tid & 31;
    const int l16 = lane & 15;
    const int hi8 = (lane >> 4) << 3;
    const int row0 = blockIdx.x * 128;
    const int m0 = wid * 16;

    float4 aR8[8];
    auto loadA = [&](int k0) {
        #pragma unroll
        for (int i = 0; i < 8; i++) {
            int idx = tid + i * 256;
            int r = idx >> 4, cg = idx & 15;
            aR8[i] = *reinterpret_cast<const float4*>(
                X + (size_t)(row0 + r) * DEMB + k0 + cg * 4);
        }
    };
    auto convA = [&](int s) {
        const uint32_t aB = base + s * ABUF;
        #pragma unroll
        for (int i = 0; i < 8; i++) {
            int idx = tid + i * 256;
            int r = idx >> 4, cg = idx & 15;
            float4 t = aR8[i];
            uint32_t h0 = cvt2h(t.x, t.y);
            uint32_t h1 = cvt2h(t.z, t.w);
            uint32_t off = (uint32_t)(r * APAD + cg * 4) * 2;
            asm volatile("st.shared.v2.b32 [%0], {%1, %2};" :: "r"(aB + off), "r"(h0), "r"(h1) : "memory");
        }
    };
    auto cpB = [&](int c, int s) {
        const uint32_t bHi = bBase + s * BBUF;
        const int k0 = c * KC;
        #pragma unroll
        for (int i = 0; i < 2; i++) {
            int rem = tid + i * 256;
            int r = rem >> 3, cq = rem & 7;
            cp_async16(bHi + r * 144 + cq * 16,
                       Wh + (size_t)(k0 + r) * HEAD + cq * 8);
        }
        CP_COMMIT();
    };

    float acc[8][4] = {};

    loadA(0);
    cpB(0, 0);

    for (int c = 0; c < NCH; c++) {
        const int s = c & 1;
        convA(s);
        if (c + 1 < NCH) loadA((c + 1) * KC);
        CP_WAIT(0);
        __syncthreads();
        if (c + 1 < NCH) cpB(c + 1, s ^ 1);

        const uint32_t aB  = base + s * ABUF;
        const uint32_t bHi = bBase + s * BBUF;
        #pragma unroll
        for (int kk = 0; kk < 4; kk++) {
            uint32_t af[4];
            uint32_t aoff = (uint32_t)(((m0 + l16) * APAD + kk * 16 + hi8) * 2);
            ldsm_x4(af, aB + aoff);
            #pragma unroll
            for (int nb = 0; nb < 4; nb++) {
                uint32_t bh[4];
                uint32_t boff = (uint32_t)(((kk * 16 + l16) * APAD + nb * 16 + hi8) * 2);
                ldsm_x4_trans(bh, bHi + boff);
                mma_f16(acc[2 * nb + 0], af, bh + 0);
                mma_f16(acc[2 * nb + 1], af, bh + 2);
            }
        }
    }

    const int r = lane >> 2;
    const int cc = (lane & 3) * 2;
    const size_t rA = (size_t)(row0 + m0 + r) * HEAD;
    const size_t rB = (size_t)(row0 + m0 + r + 8) * HEAD;
    __half* outH = (which == 0) ? g_qh : (which == 1) ? g_kh : g_vh;
    #pragma unroll
    for (int j = 0; j < 8; j++) {
        *reinterpret_cast<uint32_t*>(&outH[rA + j * 8 + cc]) =
            cvt2h(acc[j][0] * postmul, acc[j][1] * postmul);
        *reinterpret_cast<uint32_t*>(&outH[rB + j * 8 + cc]) =
            cvt2h(acc[j][2] * postmul, acc[j][3] * postmul);
    }
}

// ===========================================================================
// Kernel 2: flash attention (R14 winner + 2 micro-cuts):
//  - mask pre-loaded into a per-thread 16-bit register (no LDG in loop)
//  - ex2.approx.ftz for all exponentials
// 128-wide key tiles, 3-stage ring, PV one round behind, exp2 softmax.
// grid = (SEQ/64, BATCH), block = 128.
// ===========================================================================
#define AP 72
#define BUF2 (128 * AP * 2)
#define STAGE2 (2 * BUF2)
#define NST 3
#define ATTN_SMEM (NST * STAGE2 + 512)  // 111104 B
#define NT2 (SEQ / 128)

__global__ __launch_bounds__(128) void attn_mma_kernel(
    const int* __restrict__ mask, float* __restrict__ out)
{
    extern __shared__ __align__(16) char smc[];
    const uint32_t smemB = smem_to_u32(smc);
    float* biasS = reinterpret_cast<float*>(smc + NST * STAGE2);

    const int b  = blockIdx.y;
    const int q0 = blockIdx.x * 64;
    const size_t base = (size_t)b * SEQ * HEAD;

    const int tid  = threadIdx.x;
    const int wid  = tid >> 5;
    const int lane = tid & 31;
    const int l16  = lane & 15;
    const int hi8  = (lane >> 4) << 3;
    const int m0   = wid * 16;
    const int c2   = (lane & 3) * 2;

    const int krow = (lane & 7) + ((lane & 16) >> 1);
    const int hcol = (lane & 8);

    // pre-load all 16 mask words for this thread's bias column -> bit register
    uint32_t mbits = 0;
    #pragma unroll
    for (int t = 0; t < NT2; t++) {
        if (mask[(size_t)b * SEQ + t * 128 + tid] != 0) mbits |= (1u << t);
    }

    // stage Q (fits inside stage-0 region; consumed before prefetch(0))
    #pragma unroll
    for (int i = 0; i < 4; i++) {
        int idx = tid + i * 128;
        int r = idx >> 3, cq = idx & 7;
        uint4 th = *reinterpret_cast<const uint4*>(g_qh + base + (size_t)(q0 + r) * HEAD + cq * 8);
        *reinterpret_cast<uint4*>(smc + r * 144 + cq * 16) = th;
    }
    __syncthreads();
    uint32_t qh[4][4];
    #pragma unroll
    for (int kh = 0; kh < 4; kh++) {
        uint32_t aoff = (uint32_t)(((m0 + l16) * AP + kh * 16 + hi8) * 2);
        ldsm_x4(qh[kh], smemB + aoff);
    }
    __syncthreads();

    const __half* srcs[2] = {g_kh + base, g_vh + base};
    auto prefetch = [&](int t) {
        const uint32_t st = smemB + (t % NST) * STAGE2;
        const int k0 = t * 128;
        #pragma unroll
        for (int i = 0; i < 16; i++) {
            const int buf = i >> 3;
            int rem = tid + (i & 7) * 128;
            int r = rem >> 3, cq = rem & 7;
            cp_async16(st + buf * BUF2 + r * 144 + cq * 16,
                       srcs[buf] + (size_t)(k0 + r) * HEAD + cq * 8);
        }
        CP_COMMIT();
    };

    prefetch(0);

    const float NEG_INF = __int_as_float(0xff800000);
    float mR0 = NEG_INF, mR1 = NEG_INF, lS0 = 0.f, lS1 = 0.f;
    float o[8][4] = {};
    uint32_t pPrev[8][4];

    for (int kt = 0; kt < NT2; kt++) {
        const uint32_t stK = smemB + (kt % NST) * STAGE2;

        CP_WAIT(0);
        biasS[tid] = ((mbits >> kt) & 1u) ? 0.f : -1e30f;
        __syncthreads();
        if (kt + 1 < NT2) prefetch(kt + 1);

        // ---- S(t) = Qh @ Kh^T over 128 keys ----
        float sF[16][4] = {};
        #pragma unroll
        for (int kh = 0; kh < 4; kh++) {
            #pragma unroll
            for (int nb = 0; nb < 8; nb++) {
                uint32_t bh[4];
                uint32_t boff = (uint32_t)(((nb * 16 + krow) * AP + kh * 16 + hcol) * 2);
                ldsm_x4(bh, stK + boff);
                mma_f16(sF[2 * nb],     qh[kh], bh);
                mma_f16(sF[2 * nb + 1], qh[kh], bh + 2);
            }
        }

        // ---- PV(t-1): tensor pipe busy under softmax below ----
        if (kt > 0) {
            const uint32_t stVp = smemB + ((kt - 1) % NST) * STAGE2 + BUF2;
            #pragma unroll
            for (int kb = 0; kb < 8; kb++) {
                #pragma unroll
                for (int nb = 0; nb < 4; nb++) {
                    uint32_t vh[4];
                    uint32_t boff = (uint32_t)(((kb * 16 + l16) * AP + nb * 16 + hi8) * 2);
                    ldsm_x4_trans(vh, stVp + boff);
                    mma_f16(o[2 * nb],     pPrev[kb], vh);
                    mma_f16(o[2 * nb + 1], pPrev[kb], vh + 2);
                }
            }
        }

        // ---- softmax(t) in exp2 domain (MUFU approx) ----
        float mx0 = NEG_INF, mx1 = NEG_INF;
        #pragma unroll
        for (int j = 0; j < 16; j++) {
            float2 bv = *reinterpret_cast<float2*>(&biasS[j * 8 + c2]);
            sF[j][0] += bv.x; sF[j][1] += bv.y; sF[j][2] += bv.x; sF[j][3] += bv.y;
            mx0 = fmaxf(mx0, fmaxf(sF[j][0], sF[j][1]));
            mx1 = fmaxf(mx1, fmaxf(sF[j][2], sF[j][3]));
        }
        mx0 = fmaxf(mx0, __shfl_xor_sync(0xffffffffu, mx0, 1));
        mx0 = fmaxf(mx0, __shfl_xor_sync(0xffffffffu, mx0, 2));
        mx1 = fmaxf(mx1, __shfl_xor_sync(0xffffffffu, mx1, 1));
        mx1 = fmaxf(mx1, __shfl_xor_sync(0xffffffffu, mx1, 2));
        float mn0 = fmaxf(mR0, mx0), mn1 = fmaxf(mR1, mx1);
        float a0 = ex2(mR0 - mn0), a1 = ex2(mR1 - mn1);
        float sm0 = 0.f, sm1 = 0.f;
        #pragma unroll
        for (int j = 0; j < 16; j++) {
            sF[j][0] = ex2(sF[j][0] - mn0);
            sF[j][1] = ex2(sF[j][1] - mn0);
            sF[j][2] = ex2(sF[j][2] - mn1);
            sF[j][3] = ex2(sF[j][3] - mn1);
            sm0 += sF[j][0] + sF[j][1];
            sm1 += sF[j][2] + sF[j][3];
        }
        sm0 += __shfl_xor_sync(0xffffffffu, sm0, 1);
        sm0 += __shfl_xor_sync(0xffffffffu, sm0, 2);
        sm1 += __shfl_xor_sync(0xffffffffu, sm1, 1);
        sm1 += __shfl_xor_sync(0xffffffffu, sm1, 2);
        lS0 = lS0 * a0 + sm0; lS1 = lS1 * a1 + sm1;
        mR0 = mn0; mR1 = mn1;
        #pragma unroll
        for (int j = 0; j < 8; j++) {
            o[j][0] *= a0; o[j][1] *= a0; o[j][2] *= a1; o[j][3] *= a1;
        }

        // ---- pack P(t) for next round's PV ----
        #pragma unroll
        for (int kb = 0; kb < 8; kb++) {
            pPrev[kb][0] = cvt2h(sF[2 * kb][0],     sF[2 * kb][1]);
            pPrev[kb][1] = cvt2h(sF[2 * kb][2],     sF[2 * kb][3]);
            pPrev[kb][2] = cvt2h(sF[2 * kb + 1][0], sF[2 * kb + 1][1]);
            pPrev[kb][3] = cvt2h(sF[2 * kb + 1][2], sF[2 * kb + 1][3]);
        }
        __syncthreads();
    }

    // ---- final PV flush for tile NT2-1 ----
    {
        const uint32_t stVp = smemB + ((NT2 - 1) % NST) * STAGE2 + BUF2;
        #pragma unroll
        for (int kb = 0; kb < 8; kb++) {
            #pragma unroll
            for (int nb = 0; nb < 4; nb++) {
                uint32_t vh[4];
                uint32_t boff = (uint32_t)(((kb * 16 + l16) * AP + nb * 16 + hi8) * 2);
                ldsm_x4_trans(vh, stVp + boff);
                mma_f16(o[2 * nb],     pPrev[kb], vh);
                mma_f16(o[2 * nb + 1], pPrev[kb], vh + 2);
            }
        }
    }

    float inv0 = 1.f / lS0, inv1 = 1.f / lS1;
    int rowA = b * SEQ + q0 + m0 + (lane >> 2);
    #pragma unroll
    for (int j = 0; j < 8; j++) {
        *reinterpret_cast<float2*>(out + (size_t)rowA * HEAD + j * 8 + c2) =
            make_float2(o[j][0] * inv0, o[j][1] * inv0);
        *reinterpret_cast<float2*>(out + (size_t)(rowA + 8) * HEAD + j * 8 + c2) =
            make_float2(o[j][2] * inv1, o[j][3] * inv1);
    }
}

// ---------------------------------------------------------------------------
extern "C" void kernel_launch(void* const* d_in, const int* in_sizes, int n_in,
                              void* d_out, int out_size)
{
    const void* big[3]   = {0, 0, 0};
    const void* small[3] = {0, 0, 0};
    const void* mk = 0;
    int nb = 0, ns = 0;
    for (int i = 0; i < n_in; i++) {
        if (in_sizes[i] == NROWS * DEMB)      { if (nb < 3) big[nb++] = d_in[i]; }
        else if (in_sizes[i] == DEMB * HEAD)  { if (ns < 3) small[ns++] = d_in[i]; }
        else if (in_sizes[i] == BATCH * SEQ)  { mk = d_in[i]; }
    }
    const float* q  = (const float*)big[0];
    const float* k  = (const float*)big[1];
    const float* v  = (const float*)big[2];
    const float* Wq = (const float*)small[0];
    const float* Wk = (const float*)small[1];
    const float* Wv = (const float*)small[2];
    const int*   mask = (const int*)mk;
    float* out = (float*)d_out;

    static bool attr_set = false;
    if (!attr_set) {
        cudaFuncSetAttribute(proj_mma_kernel, cudaFuncAttributeMaxDynamicSharedMemorySize, PROJ_SMEM);
        cudaFuncSetAttribute(attn_mma_kernel, cudaFuncAttributeMaxDynamicSharedMemorySize, ATTN_SMEM);
        attr_set = true;
    }

    wsplit_kernel<<<dim3(64, 3), 256>>>(Wq, Wk, Wv);
    proj_mma_kernel<<<dim3(NROWS / 128, 3), 256, PROJ_SMEM>>>(q, k, v);
    attn_mma_kernel<<<dim3(SEQ / 64, BATCH), 128, ATTN_SMEM>>>(mask, out);
}

// round 17
// speedup vs baseline: 1.1133x; 1.0218x over previous
#include <cuda_runtime.h>
#include <cuda_fp16.h>
#include <cstdint>

// Problem constants (Head_84533546320520)
#define BATCH 8
#define SEQ   2048
#define DEMB  1024
#define HEAD  64
#define NROWS (BATCH * SEQ)   // 16384
#define SCALE 0.125f          // HEAD^-0.5
#define LOG2E 1.4426950408889634f

// fp16 scratch: projected q (pre-scaled by SCALE*log2e), k, v
__device__ __half g_qh[NROWS * HEAD];
__device__ __half g_kh[NROWS * HEAD];
__device__ __half g_vh[NROWS * HEAD];

// Pre-converted weights (single fp16)
__device__ __half g_wh[3][DEMB * HEAD];

// ===========================================================================
// helpers
// ===========================================================================
__device__ __forceinline__ uint32_t smem_to_u32(const void* p) {
    uint32_t a;
    asm("{ .reg .u64 t; cvta.to.shared.u64 t, %1; cvt.u32.u64 %0, t; }"
        : "=r"(a) : "l"(p));
    return a;
}
__device__ __forceinline__ void ldsm_x4(uint32_t* r, uint32_t addr) {
    asm volatile("ldmatrix.sync.aligned.m8n8.x4.shared.b16 {%0,%1,%2,%3}, [%4];"
        : "=r"(r[0]), "=r"(r[1]), "=r"(r[2]), "=r"(r[3]) : "r"(addr));
}
__device__ __forceinline__ void ldsm_x4_trans(uint32_t* r, uint32_t addr) {
    asm volatile("ldmatrix.sync.aligned.m8n8.x4.trans.shared.b16 {%0,%1,%2,%3}, [%4];"
        : "=r"(r[0]), "=r"(r[1]), "=r"(r[2]), "=r"(r[3]) : "r"(addr));
}
__device__ __forceinline__ void mma_f16(float* d, const uint32_t* a, const uint32_t* b) {
    asm volatile(
        "mma.sync.aligned.m16n8k16.row.col.f32.f16.f16.f32 "
        "{%0,%1,%2,%3}, {%4,%5,%6,%7}, {%8,%9}, {%0,%1,%2,%3};"
        : "+f"(d[0]), "+f"(d[1]), "+f"(d[2]), "+f"(d[3])
        : "r"(a[0]), "r"(a[1]), "r"(a[2]), "r"(a[3]), "r"(b[0]), "r"(b[1]));
}
__device__ __forceinline__ uint32_t cvt2h(float x, float y) {
    __half2 hb = __float22half2_rn(make_float2(x, y));
    return *reinterpret_cast<uint32_t*>(&hb);
}
__device__ __forceinline__ float ex2(float x) {
    float y;
    asm("ex2.approx.ftz.f32 %0, %1;" : "=f"(y) : "f"(x));
    return y;
}
__device__ __forceinline__ void cp_async16(uint32_t saddr, const void* gaddr) {
    asm volatile("cp.async.cg.shared.global [%0], [%1], 16;"
        :: "r"(saddr), "l"(gaddr) : "memory");
}
#define CP_COMMIT()  asm volatile("cp.async.commit_group;" ::: "memory")
#define CP_WAIT(n)   asm volatile("cp.async.wait_group %0;" :: "n"(n) : "memory")

// ===========================================================================
// Kernel 0: convert W to fp16. grid (64, 3), block 256. (FROZEN)
// ===========================================================================
__global__ __launch_bounds__(256) void wsplit_kernel(
    const float* __restrict__ Wq, const float* __restrict__ Wk,
    const float* __restrict__ Wv)
{
    const int which = blockIdx.y;
    const float* __restrict__ W = (which == 0) ? Wq : (which == 1) ? Wk : Wv;
    int idx = blockIdx.x * 256 + threadIdx.x;
    float4 t = reinterpret_cast<const float4*>(W)[idx];
    *reinterpret_cast<uint2*>(&g_wh[which][idx * 4]) =
        make_uint2(cvt2h(t.x, t.y), cvt2h(t.z, t.w));
}

// ===========================================================================
// Kernel 1: projections — SMALLER CTAs for latency hiding:
// M=64 rows/CTA, block=128 (4 warps), grid (256, 3) = 768 CTAs (~5.2/SM).
// Same per-warp structure as the frozen R12/R14 winner.
// ===========================================================================
#define KC 64
#define NCH (DEMB / KC)           // 16
#define APAD 72
#define PM 64                     // rows per CTA
#define ABUF (PM * APAD * 2)      // 9216 B
#define BBUF (64 * APAD * 2)      // 9216 B
#define PROJ_SMEM (2 * ABUF + 2 * BBUF)   // 36864 B

__global__ __launch_bounds__(128) void proj_mma_kernel(
    const float* __restrict__ q, const float* __restrict__ k,
    const float* __restrict__ v)
{
    extern __shared__ __align__(16) char smc[];
    const uint32_t base = smem_to_u32(smc);
    const uint32_t bBase = base + 2 * ABUF;

    const int which = blockIdx.y;
    const float* __restrict__ X = (which == 0) ? q : (which == 1) ? k : v;
    const __half* __restrict__ Wh = g_wh[which];
    const float postmul = (which == 0) ? (SCALE * LOG2E) : 1.0f;

    const int tid = threadIdx.x;
    const int wid = tid >> 5;
    const int lane = tid & 31;
    const int l16 = lane & 15;
    const int hi8 = (lane >> 4) << 3;
    const int row0 = blockIdx.x * PM;
    const int m0 = wid * 16;

    float4 aR8[8];
    auto loadA = [&](int k0) {
        #pragma unroll
        for (int i = 0; i < 8; i++) {
            int idx = tid + i * 128;       // 0..1023
            int r = idx >> 4, cg = idx & 15;
            aR8[i] = *reinterpret_cast<const float4*>(
                X + (size_t)(row0 + r) * DEMB + k0 + cg * 4);
        }
    };
    auto convA = [&](int s) {
        const uint32_t aB = base + s * ABUF;
        #pragma unroll
        for (int i = 0; i < 8; i++) {
            int idx = tid + i * 128;
            int r = idx >> 4, cg = idx & 15;
            float4 t = aR8[i];
            uint32_t h0 = cvt2h(t.x, t.y);
            uint32_t h1 = cvt2h(t.z, t.w);
            uint32_t off = (uint32_t)(r * APAD + cg * 4) * 2;
            asm volatile("st.shared.v2.b32 [%0], {%1, %2};" :: "r"(aB + off), "r"(h0), "r"(h1) : "memory");
        }
    };
    auto cpB = [&](int c, int s) {
        const uint32_t bHi = bBase + s * BBUF;
        const int k0 = c * KC;
        #pragma unroll
        for (int i = 0; i < 4; i++) {
            int rem = tid + i * 128;       // 0..511
            int r = rem >> 3, cq = rem & 7;
            cp_async16(bHi + r * 144 + cq * 16,
                       Wh + (size_t)(k0 + r) * HEAD + cq * 8);
        }
        CP_COMMIT();
    };

    float acc[8][4] = {};

    loadA(0);
    cpB(0, 0);

    for (int c = 0; c < NCH; c++) {
        const int s = c & 1;
        convA(s);
        if (c + 1 < NCH) loadA((c + 1) * KC);
        CP_WAIT(0);
        __syncthreads();
        if (c + 1 < NCH) cpB(c + 1, s ^ 1);

        const uint32_t aB  = base + s * ABUF;
        const uint32_t bHi = bBase + s * BBUF;
        #pragma unroll
        for (int kk = 0; kk < 4; kk++) {
            uint32_t af[4];
            uint32_t aoff = (uint32_t)(((m0 + l16) * APAD + kk * 16 + hi8) * 2);
            ldsm_x4(af, aB + aoff);
            #pragma unroll
            for (int nb = 0; nb < 4; nb++) {
                uint32_t bh[4];
                uint32_t boff = (uint32_t)(((kk * 16 + l16) * APAD + nb * 16 + hi8) * 2);
                ldsm_x4_trans(bh, bHi + boff);
                mma_f16(acc[2 * nb + 0], af, bh + 0);
                mma_f16(acc[2 * nb + 1], af, bh + 2);
            }
        }
    }

    const int r = lane >> 2;
    const int cc = (lane & 3) * 2;
    const size_t rA = (size_t)(row0 + m0 + r) * HEAD;
    const size_t rB = (size_t)(row0 + m0 + r + 8) * HEAD;
    __half* outH = (which == 0) ? g_qh : (which == 1) ? g_kh : g_vh;
    #pragma unroll
    for (int j = 0; j < 8; j++) {
        *reinterpret_cast<uint32_t*>(&outH[rA + j * 8 + cc]) =
            cvt2h(acc[j][0] * postmul, acc[j][1] * postmul);
        *reinterpret_cast<uint32_t*>(&outH[rB + j * 8 + cc]) =
            cvt2h(acc[j][2] * postmul, acc[j][3] * postmul);
    }
}

// ===========================================================================
// Kernel 2: flash attention (R16 winner, FROZEN):
// 128-wide key tiles, 3-stage ring, PV one round behind, exp2 softmax,
// mask in bit-register, ex2.approx.
// grid = (SEQ/64, BATCH), block = 128.
// ===========================================================================
#define AP 72
#define BUF2 (128 * AP * 2)
#define STAGE2 (2 * BUF2)
#define NST 3
#define ATTN_SMEM (NST * STAGE2 + 512)  // 111104 B
#define NT2 (SEQ / 128)

__global__ __launch_bounds__(128) void attn_mma_kernel(
    const int* __restrict__ mask, float* __restrict__ out)
{
    extern __shared__ __align__(16) char smc[];
    const uint32_t smemB = smem_to_u32(smc);
    float* biasS = reinterpret_cast<float*>(smc + NST * STAGE2);

    const int b  = blockIdx.y;
    const int q0 = blockIdx.x * 64;
    const size_t base = (size_t)b * SEQ * HEAD;

    const int tid  = threadIdx.x;
    const int wid  = tid >> 5;
    const int lane = tid & 31;
    const int l16  = lane & 15;
    const int hi8  = (lane >> 4) << 3;
    const int m0   = wid * 16;
    const int c2   = (lane & 3) * 2;

    const int krow = (lane & 7) + ((lane & 16) >> 1);
    const int hcol = (lane & 8);

    uint32_t mbits = 0;
    #pragma unroll
    for (int t = 0; t < NT2; t++) {
        if (mask[(size_t)b * SEQ + t * 128 + tid] != 0) mbits |= (1u << t);
    }

    #pragma unroll
    for (int i = 0; i < 4; i++) {
        int idx = tid + i * 128;
        int r = idx >> 3, cq = idx & 7;
        uint4 th = *reinterpret_cast<const uint4*>(g_qh + base + (size_t)(q0 + r) * HEAD + cq * 8);
        *reinterpret_cast<uint4*>(smc + r * 144 + cq * 16) = th;
    }
    __syncthreads();
    uint32_t qh[4][4];
    #pragma unroll
    for (int kh = 0; kh < 4; kh++) {
        uint32_t aoff = (uint32_t)(((m0 + l16) * AP + kh * 16 + hi8) * 2);
        ldsm_x4(qh[kh], smemB + aoff);
    }
    __syncthreads();

    const __half* srcs[2] = {g_kh + base, g_vh + base};
    auto prefetch = [&](int t) {
        const uint32_t st = smemB + (t % NST) * STAGE2;
        const int k0 = t * 128;
        #pragma unroll
        for (int i = 0; i < 16; i++) {
            const int buf = i >> 3;
            int rem = tid + (i & 7) * 128;
            int r = rem >> 3, cq = rem & 7;
            cp_async16(st + buf * BUF2 + r * 144 + cq * 16,
                       srcs[buf] + (size_t)(k0 + r) * HEAD + cq * 8);
        }
        CP_COMMIT();
    };

    prefetch(0);

    const float NEG_INF = __int_as_float(0xff800000);
    float mR0 = NEG_INF, mR1 = NEG_INF, lS0 = 0.f, lS1 = 0.f;
    float o[8][4] = {};
    uint32_t pPrev[8][4];

    for (int kt = 0; kt < NT2; kt++) {
        const uint32_t stK = smemB + (kt % NST) * STAGE2;

        CP_WAIT(0);
        biasS[tid] = ((mbits >> kt) & 1u) ? 0.f : -1e30f;
        __syncthreads();
        if (kt + 1 < NT2) prefetch(kt + 1);

        float sF[16][4] = {};
        #pragma unroll
        for (int kh = 0; kh < 4; kh++) {
            #pragma unroll
            for (int nb = 0; nb < 8; nb++) {
                uint32_t bh[4];
                uint32_t boff = (uint32_t)(((nb * 16 + krow) * AP + kh * 16 + hcol) * 2);
                ldsm_x4(bh, stK + boff);
                mma_f16(sF[2 * nb],     qh[kh], bh);
                mma_f16(sF[2 * nb + 1], qh[kh], bh + 2);
            }
        }

        if (kt > 0) {
            const uint32_t stVp = smemB + ((kt - 1) % NST) * STAGE2 + BUF2;
            #pragma unroll
            for (int kb = 0; kb < 8; kb++) {
                #pragma unroll
                for (int nb = 0; nb < 4; nb++) {
                    uint32_t vh[4];
                    uint32_t boff = (uint32_t)(((kb * 16 + l16) * AP + nb * 16 + hi8) * 2);
                    ldsm_x4_trans(vh, stVp + boff);
                    mma_f16(o[2 * nb],     pPrev[kb], vh);
                    mma_f16(o[2 * nb + 1], pPrev[kb], vh + 2);
                }
            }
        }

        float mx0 = NEG_INF, mx1 = NEG_INF;
        #pragma unroll
        for (int j = 0; j < 16; j++) {
            float2 bv = *reinterpret_cast<float2*>(&biasS[j * 8 + c2]);
            sF[j][0] += bv.x; sF[j][1] += bv.y; sF[j][2] += bv.x; sF[j][3] += bv.y;
            mx0 = fmaxf(mx0, fmaxf(sF[j][0], sF[j][1]));
            mx1 = fmaxf(mx1, fmaxf(sF[j][2], sF[j][3]));
        }
        mx0 = fmaxf(mx0, __shfl_xor_sync(0xffffffffu, mx0, 1));
        mx0 = fmaxf(mx0, __shfl_xor_sync(0xffffffffu, mx0, 2));
        mx1 = fmaxf(mx1, __shfl_xor_sync(0xffffffffu, mx1, 1));
        mx1 = fmaxf(mx1, __shfl_xor_sync(0xffffffffu, mx1, 2));
        float mn0 = fmaxf(mR0, mx0), mn1 = fmaxf(mR1, mx1);
        float a0 = ex2(mR0 - mn0), a1 = ex2(mR1 - mn1);
        float sm0 = 0.f, sm1 = 0.f;
        #pragma unroll
        for (int j = 0; j < 16; j++) {
            sF[j][0] = ex2(sF[j][0] - mn0);
            sF[j][1] = ex2(sF[j][1] - mn0);
            sF[j][2] = ex2(sF[j][2] - mn1);
            sF[j][3] = ex2(sF[j][3] - mn1);
            sm0 += sF[j][0] + sF[j][1];
            sm1 += sF[j][2] + sF[j][3];
        }
        sm0 += __shfl_xor_sync(0xffffffffu, sm0, 1);
        sm0 += __shfl_xor_sync(0xffffffffu, sm0, 2);
        sm1 += __shfl_xor_sync(0xffffffffu, sm1, 1);
        sm1 += __shfl_xor_sync(0xffffffffu, sm1, 2);
        lS0 = lS0 * a0 + sm0; lS1 = lS1 * a1 + sm1;
        mR0 = mn0; mR1 = mn1;
        #pragma unroll
        for (int j = 0; j < 8; j++) {
            o[j][0] *= a0; o[j][1] *= a0; o[j][2] *= a1; o[j][3] *= a1;
        }

        #pragma unroll
        for (int kb = 0; kb < 8; kb++) {
            pPrev[kb][0] = cvt2h(sF[2 * kb][0],     sF[2 * kb][1]);
            pPrev[kb][1] = cvt2h(sF[2 * kb][2],     sF[2 * kb][3]);
            pPrev[kb][2] = cvt2h(sF[2 * kb + 1][0], sF[2 * kb + 1][1]);
            pPrev[kb][3] = cvt2h(sF[2 * kb + 1][2], sF[2 * kb + 1][3]);
        }
        __syncthreads();
    }

    {
        const uint32_t stVp = smemB + ((NT2 - 1) % NST) * STAGE2 + BUF2;
        #pragma unroll
        for (int kb = 0; kb < 8; kb++) {
            #pragma unroll
            for (int nb = 0; nb < 4; nb++) {
                uint32_t vh[4];
                uint32_t boff = (uint32_t)(((kb * 16 + l16) * AP + nb * 16 + hi8) * 2);
                ldsm_x4_trans(vh, stVp + boff);
                mma_f16(o[2 * nb],     pPrev[kb], vh);
                mma_f16(o[2 * nb + 1], pPrev[kb], vh + 2);
            }
        }
    }

    float inv0 = 1.f / lS0, inv1 = 1.f / lS1;
    int rowA = b * SEQ + q0 + m0 + (lane >> 2);
    #pragma unroll
    for (int j = 0; j < 8; j++) {
        *reinterpret_cast<float2*>(out + (size_t)rowA * HEAD + j * 8 + c2) =
            make_float2(o[j][0] * inv0, o[j][1] * inv0);
        *reinterpret_cast<float2*>(out + (size_t)(rowA + 8) * HEAD + j * 8 + c2) =
            make_float2(o[j][2] * inv1, o[j][3] * inv1);
    }
}

// ---------------------------------------------------------------------------
extern "C" void kernel_launch(void* const* d_in, const int* in_sizes, int n_in,
                              void* d_out, int out_size)
{
    const void* big[3]   = {0, 0, 0};
    const void* small[3] = {0, 0, 0};
    const void* mk = 0;
    int nb = 0, ns = 0;
    for (int i = 0; i < n_in; i++) {
        if (in_sizes[i] == NROWS * DEMB)      { if (nb < 3) big[nb++] = d_in[i]; }
        else if (in_sizes[i] == DEMB * HEAD)  { if (ns < 3) small[ns++] = d_in[i]; }
        else if (in_sizes[i] == BATCH * SEQ)  { mk = d_in[i]; }
    }
    const float* q  = (const float*)big[0];
    const float* k  = (const float*)big[1];
    const float* v  = (const float*)big[2];
    const float* Wq = (const float*)small[0];
    const float* Wk = (const float*)small[1];
    const float* Wv = (const float*)small[2];
    const int*   mask = (const int*)mk;
    float* out = (float*)d_out;

    static bool attr_set = false;
    if (!attr_set) {
        cudaFuncSetAttribute(proj_mma_kernel, cudaFuncAttributeMaxDynamicSharedMemorySize, PROJ_SMEM);
        cudaFuncSetAttribute(attn_mma_kernel, cudaFuncAttributeMaxDynamicSharedMemorySize, ATTN_SMEM);
        attr_set = true;
    }

    wsplit_kernel<<<dim3(64, 3), 256>>>(Wq, Wk, Wv);
    proj_mma_kernel<<<dim3(NROWS / PM, 3), 128, PROJ_SMEM>>>(q, k, v);
    attn_mma_kernel<<<dim3(SEQ / 64, BATCH), 128, ATTN_SMEM>>>(mask, out);
}